// round 16
// baseline (speedup 1.0000x reference)
#include <cuda_runtime.h>
#include <float.h>

// ROI max pool, shuffle-based, ORIGINAL layout (no transpose, no reshape):
//  A) prep: per-roi metadata (roi-level + 7 band rows + 7 bin columns)
//  B) pool: warp = one (n, c). lane = ROI column (original layout rows are
//     contiguous -> coalesced loads). Per i-band: per-column max over band
//     rows in registers, then fixed 8-step clamped __shfl_sync gather
//     produces all 7 j-bin maxes (dup shuffles idempotent under max).
//     Lanes 0..6 store out[n][c][i*7+j] = 7 contiguous floats. w>32 handled
//     via second column register (warp-uniform branch, ~13% of warps).

#define OUTP 7
#define NBINS 49
#define CCH  256
#define HH   50
#define WW   50
#define HWSZ (HH * WW)

__device__ int4 g_roimeta[128];        // {im, x1, wm1, 0}
__device__ int2 g_bandmeta[128 * 8];   // [n*8+i]: {ys*WW, rows}
__device__ int2 g_binmeta[128 * 8];    // [n*8+j]: {xs_rel, len-1}

// ---------------- A) prep: one thread per roi ----------------
__global__ void prep_kernel(const float* __restrict__ rois)
{
    int n = threadIdx.x;
    if (n >= 128) return;

    const float* r = rois + n * 5;
    int im = (int)rintf(r[0]);
    int x1 = (int)rintf(r[1] * 0.0625f);
    int y1 = (int)rintf(r[2] * 0.0625f);
    int x2 = (int)rintf(r[3] * 0.0625f);
    int y2 = (int)rintf(r[4] * 0.0625f);
    unsigned h = (unsigned)(y2 - y1 + 1);
    unsigned w = (unsigned)(x2 - x1 + 1);

    g_roimeta[n] = make_int4(im, x1, (int)w - 1, 0);

    #pragma unroll
    for (int i = 0; i < OUTP; ++i) {
        int ys = (int)((unsigned)(i * h) / 7u) + y1;
        int ye = (int)(((unsigned)((i + 1) * h) + 6u) / 7u) + y1;
        ye = min(ye, HH);
        g_bandmeta[n * 8 + i] = make_int2(ys * WW, ye - ys);
    }
    #pragma unroll
    for (int j = 0; j < OUTP; ++j) {
        int xs = (int)((unsigned)(j * w) / 7u);              // rel to x1
        int xe = (int)(((unsigned)((j + 1) * w) + 6u) / 7u); // rel to x1
        xe = min(xe, WW - x1);
        g_binmeta[n * 8 + j] = make_int2(xs, xe - xs - 1);
    }
}

// ---------------- B) pool: grid (32, 128), 256 thr = 8 warps ----------------
// warp -> channel c = blockIdx.x*8 + warpid; all warps of a block share n.
__global__ __launch_bounds__(256) void roi_pool_kernel(
    const float* __restrict__ feat, float* __restrict__ out)
{
    int n    = blockIdx.y;
    int c    = blockIdx.x * 8 + (threadIdx.x >> 5);
    int lane = threadIdx.x & 31;

    int4 rm = __ldg(&g_roimeta[n]);          // im, x1, wm1
    int wm1 = rm.z;
    bool wide = (wm1 >= 32);                 // warp-uniform

    const float* plane = feat + (rm.x * CCH + c) * HWSZ;
    const float* colA  = plane + rm.y + min(lane, wm1);
    const float* colB  = plane + rm.y + 32 + min(lane, max(wm1 - 32, 0));

    // per-lane bin meta (lanes 7..31 harmlessly read j=6)
    int2 bm    = __ldg(&g_binmeta[n * 8 + min(lane, 6)]);
    int  xs    = bm.x;
    int  lenm1 = bm.y;                       // 0..7

    float* dst = out + (n * CCH + c) * NBINS;

    #pragma unroll
    for (int i = 0; i < OUTP; ++i) {
        int2 band = __ldg(&g_bandmeta[n * 8 + i]);   // {ys*WW, rows} uniform
        const float* p = colA + band.x;

        // per-column max over band rows (coalesced 128B row segments)
        float cm = __ldg(p);
        for (int r = 1; r < band.y; ++r)
            cm = fmaxf(cm, __ldg(p + r * WW));

        float m = -FLT_MAX;
        if (!wide) {
            #pragma unroll
            for (int k = 0; k < 8; ++k) {
                int src = xs + min(k, lenm1);          // clamped dup = ok
                m = fmaxf(m, __shfl_sync(0xffffffffu, cm, src));
            }
        } else {
            const float* pb = colB + band.x;
            float cmB = __ldg(pb);
            for (int r = 1; r < band.y; ++r)
                cmB = fmaxf(cmB, __ldg(pb + r * WW));
            #pragma unroll
            for (int k = 0; k < 8; ++k) {
                int src = xs + min(k, lenm1);
                float va = __shfl_sync(0xffffffffu, cm,  src & 31);
                float vb = __shfl_sync(0xffffffffu, cmB, src & 31);
                m = fmaxf(m, (src < 32) ? va : vb);
            }
        }

        if (lane < OUTP)
            dst[i * OUTP + lane] = m;        // 7 contiguous floats per warp
    }
}

extern "C" void kernel_launch(void* const* d_in, const int* in_sizes, int n_in,
                              void* d_out, int out_size)
{
    const float* feat = (const float*)d_in[0];
    const float* rois = (const float*)d_in[1];
    float* out = (float*)d_out;

    prep_kernel<<<1, 128>>>(rois);

    roi_pool_kernel<<<dim3(32, 128), 256>>>(feat, out);
}

// round 17
// speedup vs baseline: 1.2453x; 1.2453x over previous
#include <cuda_runtime.h>
#include <float.h>

// ROI max pool — SINGLE persistent kernel, software grid barrier.
// 148 CTAs x 512 threads (grid <= SM count -> all co-resident).
//   Phase 1: per-(roi,bin) meta (6272 threads) + grid-stride register
//            transpose feat [2,256,50,50] -> g_feat_t [2,50,50,256].
//   Barrier: counting barrier on g_bar0 (self-resetting for graph replay).
//   Phase 2: dynamic task queue (g_taskctr). task = (roi n, 128-ch group).
//            warp = bin x 128 ch (lanes = channel float4, proven coalesced),
//            chunked clamped unrolled loads (width<=8), smem stage,
//            coalesced epilogue to out[n][c][ij]. No scratch output tensor.

#define OUTP 7
#define NBINS 49
#define CCH  256
#define HH   50
#define WW   50
#define HWSZ (HH * WW)
#define CS4  (CCH / 4)         // 64
#define RS4  (WW * CS4)        // 3200

#define NCTA 148
#define NTHR 512
#define NTASK 256              // 128 rois x 2 ch-groups
#define TUNITS (1264 * 256)    // transpose thread-units: 323584
#define GSTRIDE (NCTA * NTHR)  // 75776

__device__ __align__(16) float g_feat_t[2 * HWSZ * CCH];   // 5.12 MB
__device__ int4 g_meta[128 * NBINS];
__device__ unsigned g_bar0 = 0;
__device__ unsigned g_bar1 = 0;
__device__ unsigned g_taskctr = 0;

__device__ __forceinline__ float4 fmax4(float4 a, float4 b)
{
    return make_float4(fmaxf(a.x, b.x), fmaxf(a.y, b.y),
                       fmaxf(a.z, b.z), fmaxf(a.w, b.w));
}

__global__ __launch_bounds__(NTHR, 1) void roi_fused_kernel(
    const float* __restrict__ feat, const float* __restrict__ rois,
    float* __restrict__ out)
{
    __shared__ __align__(16) float s[NBINS * 132];
    __shared__ int s_task;

    unsigned gtid = blockIdx.x * NTHR + threadIdx.x;

    // ---- Phase 1a: meta ----
    if (gtid < 128 * NBINS) {
        int n  = gtid / NBINS;
        int ij = gtid - n * NBINS;
        int i  = ij / OUTP;
        int j  = ij - i * OUTP;

        const float* r = rois + n * 5;
        int im = (int)rintf(r[0]);
        int x1 = (int)rintf(r[1] * 0.0625f);
        int y1 = (int)rintf(r[2] * 0.0625f);
        int x2 = (int)rintf(r[3] * 0.0625f);
        int y2 = (int)rintf(r[4] * 0.0625f);
        unsigned h = (unsigned)(y2 - y1 + 1);
        unsigned w = (unsigned)(x2 - x1 + 1);

        int ys = (int)((unsigned)(i * h) / 7u) + y1;
        int ye = (int)(((unsigned)((i + 1) * h) + 6u) / 7u) + y1;
        int xs = (int)((unsigned)(j * w) / 7u) + x1;
        int xe = (int)(((unsigned)((j + 1) * w) + 6u) / 7u) + x1;
        ye = min(ye, HH);  xe = min(xe, WW);

        int4 m;
        m.x = im * HWSZ + ys * WW + xs;
        m.y = ye - ys;
        m.z = xe - xs - 1;
        m.w = 0;
        g_meta[gtid] = m;
    }

    // ---- Phase 1b: register transpose (grid-stride, unrolled) ----
    #pragma unroll
    for (int k = 0; k < 5; ++k) {
        unsigned v = gtid + (unsigned)k * GSTRIDE;
        if (v < TUNITS) {
            unsigned bi  = v >> 8;
            unsigned tix = v & 255u;
            unsigned b   = bi / 632u;          // 632 = 79*8
            unsigned rem = bi - b * 632u;
            unsigned cy  = rem / 79u;
            unsigned hx  = rem - cy * 79u;
            unsigned c0   = cy * 32u + (tix >> 5) * 4u;
            unsigned lane = tix & 31u;
            unsigned hw   = hx * 32u + lane;
            if (hw < HWSZ) {
                const float* src = feat + (b * CCH + c0) * HWSZ + hw;
                float4 o;
                o.x = __ldg(src);
                o.y = __ldg(src + HWSZ);
                o.z = __ldg(src + 2 * HWSZ);
                o.w = __ldg(src + 3 * HWSZ);
                *(float4*)(g_feat_t + ((b * HWSZ + hw) * CCH + c0)) = o;
            }
        }
    }

    // ---- Grid barrier ----
    __syncthreads();
    if (threadIdx.x == 0) {
        __threadfence();
        atomicAdd(&g_bar0, 1u);
        while (atomicAdd(&g_bar0, 0u) < (unsigned)NCTA)
            __nanosleep(64);
    }
    __syncthreads();
    __threadfence();   // acquire: transposed data + meta now visible

    // ---- Phase 2: pool via dynamic task queue ----
    int lane = threadIdx.x & 31;
    int wrp  = threadIdx.x >> 5;               // 0..15

    for (;;) {
        if (threadIdx.x == 0)
            s_task = (int)atomicAdd(&g_taskctr, 1u);
        __syncthreads();
        int t = s_task;
        if (t >= NTASK) break;

        int n  = t >> 1;
        int cg = t & 1;

        for (int ij = wrp; ij < NBINS; ij += 16) {
            int4 m = __ldg(&g_meta[n * NBINS + ij]);
            int wm1 = m.z;
            const float4* base = (const float4*)g_feat_t
                               + (unsigned)(m.x * CS4 + cg * 32 + lane);
            int o1 = min(1, wm1) * CS4;
            int o2 = min(2, wm1) * CS4;
            int o3 = min(3, wm1) * CS4;
            int o5 = min(5, wm1) * CS4;
            int o6 = min(6, wm1) * CS4;
            int o7 = min(7, wm1) * CS4;

            float4 acc = make_float4(-FLT_MAX, -FLT_MAX, -FLT_MAX, -FLT_MAX);
            int rows = m.y;
            for (int r = 0; r < rows; ++r) {
                const float4* row = base + r * RS4;
                float4 v0 = __ldg(row);
                float4 v1 = __ldg(row + o1);
                float4 v2 = __ldg(row + o2);
                float4 v3 = __ldg(row + o3);
                acc = fmax4(acc, fmax4(fmax4(v0, v1), fmax4(v2, v3)));
                if (wm1 >= 4) {                 // warp-uniform
                    v0 = __ldg(row + 4 * CS4);
                    v1 = __ldg(row + o5);
                    v2 = __ldg(row + o6);
                    v3 = __ldg(row + o7);
                    acc = fmax4(acc, fmax4(fmax4(v0, v1), fmax4(v2, v3)));
                }
            }
            *(float4*)&s[ij * 132 + lane * 4] = acc;
        }
        __syncthreads();

        // coalesced epilogue: out[n][cg*128 + c][ij], 128 runs of 49 floats
        float* dst = out + (unsigned)(n * CCH + cg * 128) * NBINS;
        for (int p = threadIdx.x; p < 128 * NBINS; p += NTHR) {
            int c  = p / NBINS;
            int ij = p - c * NBINS;
            dst[p] = s[ij * 132 + c];
        }
        __syncthreads();
    }

    // ---- self-reset for next graph replay (last CTA out) ----
    if (threadIdx.x == 0) {
        unsigned v = atomicAdd(&g_bar1, 1u);
        if (v == (unsigned)(NCTA - 1)) {
            atomicExch(&g_taskctr, 0u);
            atomicExch(&g_bar0, 0u);
            atomicExch(&g_bar1, 0u);
        }
    }
}

extern "C" void kernel_launch(void* const* d_in, const int* in_sizes, int n_in,
                              void* d_out, int out_size)
{
    const float* feat = (const float*)d_in[0];
    const float* rois = (const float*)d_in[1];
    float* out = (float*)d_out;

    roi_fused_kernel<<<NCTA, NTHR>>>(feat, rois, out);
}